// round 7
// baseline (speedup 1.0000x reference)
#include <cuda_runtime.h>
#include <cstdint>

#define NB 4
#define NC 64
#define NH 128
#define NW 128
#define NPIX (NH*NW)
#define NWIN 31
#define NL (NWIN*NWIN)

typedef unsigned long long u64;

// proj slot order: 0=ql 1=kh 2=vh 3=qh 4=kl 5=vl  (dir0 uses 0,1,2; dir1 uses 3,4,5)
__device__ float g_proj[6*NB*NC*NPIX];
__device__ float g_acc_l[NB*NC*NPIX];
__device__ float g_acc_h[NB*NC*NPIX];
__device__ float g_mean[NB*NC];
__device__ float g_sgate[NB*NC];

// ---------------- packed f32x2 helpers (proj/epi) ----------------
__device__ __forceinline__ u64 pk2(float lo, float hi) {
    u64 r;
    asm("mov.b64 %0,{%1,%2};" : "=l"(r) : "f"(lo), "f"(hi));
    return r;
}
__device__ __forceinline__ void upk2(float& lo, float& hi, u64 v) {
    asm("mov.b64 {%0,%1},%2;" : "=f"(lo), "=f"(hi) : "l"(v));
}
__device__ __forceinline__ u64 fma2(u64 a, u64 b, u64 c) {
    u64 d;
    asm("fma.rn.f32x2 %0,%1,%2,%3;" : "=l"(d) : "l"(a), "l"(b), "l"(c));
    return d;
}

// ---------------- tf32 mma helpers ----------------
__device__ __forceinline__ uint32_t tf32r(float f) {
    uint32_t r;
    asm("cvt.rna.tf32.f32 %0,%1;" : "=r"(r) : "f"(f));
    return r;
}
__device__ __forceinline__ float ex2(float x) {
    float r;
    asm("ex2.approx.f32 %0,%1;" : "=f"(r) : "f"(x));
    return r;
}
__device__ __forceinline__ void mma8(float* d, const uint32_t* a, uint32_t b0, uint32_t b1) {
    asm volatile(
        "mma.sync.aligned.m16n8k8.row.col.f32.tf32.tf32.f32 "
        "{%0,%1,%2,%3},{%4,%5,%6,%7},{%8,%9},{%0,%1,%2,%3};"
        : "+f"(d[0]), "+f"(d[1]), "+f"(d[2]), "+f"(d[3])
        : "r"(a[0]), "r"(a[1]), "r"(a[2]), "r"(a[3]), "r"(b0), "r"(b1));
}
// split a float into tf32 hi + tf32 lo (hi readable as f32 bit pattern)
__device__ __forceinline__ void tsplit(float x, uint32_t& hi, uint32_t& lo) {
    hi = tf32r(x);
    lo = tf32r(x - __uint_as_float(hi));
}

// ---------------- SE: per-channel global mean ----------------
__global__ void mean_kernel(const float* __restrict__ high) {
    int bc = blockIdx.x;
    const float* p = high + (size_t)bc * NPIX;
    float s = 0.f;
    for (int i = threadIdx.x; i < NPIX; i += 256) s += p[i];
    __shared__ float red[256];
    red[threadIdx.x] = s; __syncthreads();
    for (int k = 128; k > 0; k >>= 1) {
        if (threadIdx.x < k) red[threadIdx.x] += red[threadIdx.x + k];
        __syncthreads();
    }
    if (threadIdx.x == 0) g_mean[bc] = red[0] * (1.f/NPIX);
}

// ---------------- SE: gate per (b,c) ----------------
__global__ void se_kernel(const float* __restrict__ w10, const float* __restrict__ w20,
                          const float* __restrict__ w11, const float* __restrict__ w21,
                          const float* __restrict__ w12, const float* __restrict__ w22) {
    int t = threadIdx.x;
    int b = t >> 6, c = t & 63;
    int g  = (c < 22) ? 0 : ((c < 43) ? 1 : 2);
    int of = (g == 0) ? 0 : ((g == 1) ? 22 : 43);
    int gc = (g == 0) ? 22 : 21;
    const float* w1 = (g==0) ? w10 : ((g==1) ? w11 : w12);
    const float* w2 = (g==0) ? w20 : ((g==1) ? w21 : w22);
    float h = 0.f;
    for (int j = 0; j < gc; j++) h += g_mean[b*64 + of + j] * w1[j];
    h = fmaxf(h, 0.f);
    float v = h * w2[c - of];
    g_sgate[t] = 1.f / (1.f + __expf(-v));
}

// ---------------- global projections (fma2; q-weights pre-scaled by 0.25*log2e) ----------------
#define WTS 68
#define QS 0.36067376022224085f
__global__ void __launch_bounds__(256,2) proj_kernel(
    const float* __restrict__ low, const float* __restrict__ high,
    const float* __restrict__ w_ql, const float* __restrict__ w_kh,
    const float* __restrict__ w_vh, const float* __restrict__ w_qh,
    const float* __restrict__ w_kl, const float* __restrict__ w_vl)
{
    extern __shared__ float sm[];
    float* xl = sm;            // 4096
    float* xh = sm + 4096;     // 4096
    float* wt = sm + 8192;     // 3 * 64*68

    int t = threadIdx.x;
    int pix0 = blockIdx.x * 64;
    int b = blockIdx.y;

    for (int i4 = t; i4 < 1024; i4 += 256) {
        int c = i4 >> 4, pp = (i4 & 15) * 4;
        size_t gi = (size_t)(b*NC + c)*NPIX + pix0 + pp;
        float4 vl = *(const float4*)(low + gi);
        float4 vh = *(const float4*)(high + gi);
        float gt = g_sgate[b*64 + c];
        vh.x *= gt; vh.y *= gt; vh.z *= gt; vh.w *= gt;
        *(float4*)(xl + c*64 + pp) = vl;
        *(float4*)(xh + c*64 + pp) = vh;
    }

    int ot = (t >> 4) << 2;
    int nb = (t & 15) << 2;

    for (int g = 0; g < 2; g++) {
        __syncthreads();
        const float* W0 = g ? w_kh : w_ql;
        const float* W1 = g ? w_vh : w_kl;
        const float* W2 = g ? w_qh : w_vl;
        for (int i = t; i < 12288; i += 256) {
            int p = i >> 12, j = i & 4095;
            int o = j >> 6, c = j & 63;
            const float* Wp = (p == 0) ? W0 : ((p == 1) ? W1 : W2);
            float wv = Wp[j];
            if ((g == 0 && p == 0) || (g == 1 && p == 2)) wv *= QS;
            wt[p*4352 + c*WTS + o] = wv;
        }
        __syncthreads();
        const float* Xs = g ? xh : xl;

        u64 acc2[3][4][2];
        #pragma unroll
        for (int p = 0; p < 3; p++)
            #pragma unroll
            for (int n = 0; n < 4; n++) { acc2[p][n][0] = 0ULL; acc2[p][n][1] = 0ULL; }

        #pragma unroll 2
        for (int c0 = 0; c0 < 64; c0 += 4) {
            #pragma unroll
            for (int k = 0; k < 4; k++) {
                float4 x4 = *(const float4*)(Xs + (c0+k)*64 + nb);
                u64 xd0 = pk2(x4.x, x4.x);
                u64 xd1 = pk2(x4.y, x4.y);
                u64 xd2 = pk2(x4.z, x4.z);
                u64 xd3 = pk2(x4.w, x4.w);
                #pragma unroll
                for (int p = 0; p < 3; p++) {
                    ulonglong2 w2v = *(const ulonglong2*)(wt + p*4352 + (c0+k)*WTS + ot);
                    acc2[p][0][0] = fma2(xd0, w2v.x, acc2[p][0][0]);
                    acc2[p][0][1] = fma2(xd0, w2v.y, acc2[p][0][1]);
                    acc2[p][1][0] = fma2(xd1, w2v.x, acc2[p][1][0]);
                    acc2[p][1][1] = fma2(xd1, w2v.y, acc2[p][1][1]);
                    acc2[p][2][0] = fma2(xd2, w2v.x, acc2[p][2][0]);
                    acc2[p][2][1] = fma2(xd2, w2v.y, acc2[p][2][1]);
                    acc2[p][3][0] = fma2(xd3, w2v.x, acc2[p][3][0]);
                    acc2[p][3][1] = fma2(xd3, w2v.y, acc2[p][3][1]);
                }
            }
        }
        int slots[3];
        slots[0] = g ? 1 : 0; slots[1] = g ? 2 : 4; slots[2] = g ? 3 : 5;
        #pragma unroll
        for (int p = 0; p < 3; p++) {
            float lo0[4], hi0[4], lo1[4], hi1[4];
            #pragma unroll
            for (int n = 0; n < 4; n++) {
                upk2(lo0[n], hi0[n], acc2[p][n][0]);
                upk2(lo1[n], hi1[n], acc2[p][n][1]);
            }
            size_t base = (size_t)slots[p]*NB*NC*NPIX + (size_t)(b*NC)*NPIX + pix0 + nb;
            *(float4*)(g_proj + base + (size_t)(ot+0)*NPIX) = make_float4(lo0[0],lo0[1],lo0[2],lo0[3]);
            *(float4*)(g_proj + base + (size_t)(ot+1)*NPIX) = make_float4(hi0[0],hi0[1],hi0[2],hi0[3]);
            *(float4*)(g_proj + base + (size_t)(ot+2)*NPIX) = make_float4(lo1[0],lo1[1],lo1[2],lo1[3]);
            *(float4*)(g_proj + base + (size_t)(ot+3)*NPIX) = make_float4(hi1[0],hi1[1],hi1[2],hi1[3]);
        }
    }
}

// ---------------- attention: tf32 tensor-core, one (window, dir, batch) per block ----------------
// Per warp = one head. S = Q^T K via m16n8k8 (3-term tf32 split), softmax (no max-sub,
// scale folded into q-weights at proj), O^T = V P^T via m16n8k8 (3-term), atomic fold.
// S output col j holds logical m = sigma(j) (j even: j/2, odd: j/2+4) by loading K's
// B-fragments through sigma; then S C-regs ARE the AV B-fragments (no shuffles).
__global__ void __launch_bounds__(128, 4) attn_kernel()
{
    extern __shared__ float Y[];  // q[4096] k[4096] v[4096] inv[256]
    float* sinv = Y + 12288;

    int t = threadIdx.x;
    int l = blockIdx.x, dir = blockIdx.y, b = blockIdx.z;
    int y0 = (l / NWIN) * 4, x0 = (l % NWIN) * 4;

    // stage this direction's 3 tiles (slots dir*3 + {0,1,2})
    for (int i4 = t; i4 < 3072; i4 += 128) {
        int p = i4 >> 10, rem = i4 & 1023;
        int slot = dir*3 + p;
        int c = rem >> 4, q4 = rem & 15;
        int r = q4 >> 1, cc = (q4 & 1) * 4;
        size_t gi = ((size_t)slot*NB*NC + (size_t)(b*NC + c))*NPIX + (size_t)(y0 + r)*NW + x0 + cc;
        *(float4*)(Y + p*4096 + c*64 + r*8 + cc) = *(const float4*)(g_proj + gi);
    }
    __syncthreads();

    int h = t >> 5, lane = t & 31;
    int gid = lane >> 2, tig = lane & 3;
    int sig = (gid & 1) ? ((gid >> 1) + 4) : (gid >> 1);   // sigma(gid)

    const float* Yq = Y + h*1024;
    const float* Yk = Y + 4096 + h*1024;
    const float* Yv = Y + 8192 + h*1024;
    float* gout = (dir ? g_acc_h : g_acc_l) + ((size_t)(b*NC + h*16))*NPIX;

    #pragma unroll
    for (int nt = 0; nt < 4; nt++) {
        int nbase = nt*16;
        // ---- Q A-fragments (hi/lo) for the 2 d-chunks, this n-tile ----
        uint32_t qh[2][4], ql[2][4];
        #pragma unroll
        for (int kq = 0; kq < 2; kq++) {
            int d0 = kq*8 + tig;
            tsplit(Yq[d0*64     + nbase + gid    ], qh[kq][0], ql[kq][0]);
            tsplit(Yq[d0*64     + nbase + gid + 8], qh[kq][1], ql[kq][1]);
            tsplit(Yq[(d0+4)*64 + nbase + gid    ], qh[kq][2], ql[kq][2]);
            tsplit(Yq[(d0+4)*64 + nbase + gid + 8], qh[kq][3], ql[kq][3]);
        }

        float o0[4] = {0.f,0.f,0.f,0.f};   // O tile, n = nbase + 0..7
        float o1[4] = {0.f,0.f,0.f,0.f};   // O tile, n = nbase + 8..15
        float rs0 = 0.f, rs1 = 0.f;        // row sums for n = nbase+gid, +gid+8

        #pragma unroll
        for (int mc = 0; mc < 4; mc++) {
            #pragma unroll
            for (int mt = 0; mt < 2; mt++) {
                int m8 = mc*16 + mt*8;
                // ---- S tile [n16 x m8] with 3-term tf32 ----
                float c[4] = {0.f,0.f,0.f,0.f};
                #pragma unroll
                for (int kq = 0; kq < 2; kq++) {
                    uint32_t kh0, kl0, kh1, kl1;
                    tsplit(Yk[(kq*8+tig)*64   + m8 + sig], kh0, kl0);
                    tsplit(Yk[(kq*8+tig+4)*64 + m8 + sig], kh1, kl1);
                    mma8(c, qh[kq], kh0, kh1);
                    mma8(c, qh[kq], kl0, kl1);
                    mma8(c, ql[kq], kh0, kh1);
                }
                // ---- exp, rowsum, split P ----
                float e0 = ex2(c[0]), e1 = ex2(c[1]), e2 = ex2(c[2]), e3 = ex2(c[3]);
                rs0 += e0 + e1;
                rs1 += e2 + e3;
                uint32_t ph[4], pl[4];
                tsplit(e0, ph[0], pl[0]);
                tsplit(e1, ph[1], pl[1]);
                tsplit(e2, ph[2], pl[2]);
                tsplit(e3, ph[3], pl[3]);
                // ---- V A-fragments for this m-chunk-of-8 ----
                uint32_t vh[4], vl[4];
                tsplit(Yv[gid*64     + m8 + tig    ], vh[0], vl[0]);
                tsplit(Yv[(gid+8)*64 + m8 + tig    ], vh[1], vl[1]);
                tsplit(Yv[gid*64     + m8 + tig + 4], vh[2], vl[2]);
                tsplit(Yv[(gid+8)*64 + m8 + tig + 4], vh[3], vl[3]);
                // ---- AV: O[d16 x n8] += V * P^T (3-term) ----
                mma8(o0, vh, ph[0], ph[1]);
                mma8(o0, vl, ph[0], ph[1]);
                mma8(o0, vh, pl[0], pl[1]);
                mma8(o1, vh, ph[2], ph[3]);
                mma8(o1, vl, ph[2], ph[3]);
                mma8(o1, vh, pl[2], pl[3]);
            }
        }
        // ---- softmax denominators: reduce across the 4 tig lanes ----
        rs0 += __shfl_xor_sync(0xffffffffu, rs0, 1);
        rs0 += __shfl_xor_sync(0xffffffffu, rs0, 2);
        rs1 += __shfl_xor_sync(0xffffffffu, rs1, 1);
        rs1 += __shfl_xor_sync(0xffffffffu, rs1, 2);
        if (tig == 0) {
            sinv[h*64 + nbase + gid]     = 1.f / rs0;
            sinv[h*64 + nbase + gid + 8] = 1.f / rs1;
        }
        __syncwarp();
        // ---- normalize + atomic fold ----
        #pragma unroll
        for (int jt = 0; jt < 2; jt++) {
            const float* ot = jt ? o1 : o0;
            int n0 = nbase + jt*8 + 2*tig;
            float inv0 = sinv[h*64 + n0];
            float inv1 = sinv[h*64 + n0 + 1];
            size_t pix0 = (size_t)(y0 + (n0 >> 3))*NW + x0 + (n0 & 7);
            size_t pix1 = (size_t)(y0 + ((n0+1) >> 3))*NW + x0 + ((n0+1) & 7);
            atomicAdd(gout + (size_t)gid*NPIX     + pix0, ot[0]*inv0);
            atomicAdd(gout + (size_t)gid*NPIX     + pix1, ot[1]*inv1);
            atomicAdd(gout + (size_t)(gid+8)*NPIX + pix0, ot[2]*inv0);
            atomicAdd(gout + (size_t)(gid+8)*NPIX + pix1, ot[3]*inv1);
        }
    }
}

// ---------------- epilogue: normalize fold, 1x1 proj + residual ----------------
__device__ __forceinline__ int covdim(int y) {
    int imin = (y >= 8) ? ((y - 4) >> 2) : 0;
    int imax = y >> 2; if (imax > 30) imax = 30;
    return imax - imin + 1;
}

#define WST 72

__global__ void __launch_bounds__(256) epi_kernel(
    const float* __restrict__ low, const float* __restrict__ high,
    const float* __restrict__ wpl, const float* __restrict__ wph,
    float* __restrict__ out)
{
    extern __shared__ float sm[];
    float* tl = sm;                    // 8192
    float* th = sm + 8192;             // 8192
    float* wl = sm + 16384;            // 64*WST
    float* wh = sm + 16384 + 64*WST;   // 64*WST

    int t = threadIdx.x;
    int y = blockIdx.x, b = blockIdx.y;
    float cy = (float)covdim(y);

    for (int i = t; i < 8192; i += 256) {
        int c = i >> 7, x = i & 127;
        float ic = 1.f / (cy * (float)covdim(x));
        size_t gi = ((size_t)(b*NC + c)*NH + y)*NW + x;
        tl[i] = g_acc_l[gi] * ic;
        th[i] = g_acc_h[gi] * ic;
    }
    for (int i = t; i < 4096; i += 256) {
        int o = i >> 6, c = i & 63;
        wl[c*WST + o] = wpl[i];
        wh[c*WST + o] = wph[i];
    }
    __syncthreads();

    int x = t & 127, og = (t >> 7) * 32;
    u64 rl2[16], rh2[16];
    #pragma unroll
    for (int j = 0; j < 16; j++) { rl2[j] = 0ULL; rh2[j] = 0ULL; }

    for (int c = 0; c < 64; c++) {
        float tv = tl[c*128 + x];
        float hv = th[c*128 + x];
        u64 tv2 = pk2(tv, tv);
        u64 hv2 = pk2(hv, hv);
        const ulonglong2* wlr = (const ulonglong2*)(wl + c*WST + og);
        const ulonglong2* whr = (const ulonglong2*)(wh + c*WST + og);
        #pragma unroll
        for (int o4 = 0; o4 < 8; o4++) {
            ulonglong2 a2 = wlr[o4];
            ulonglong2 b2 = whr[o4];
            rl2[o4*2]   = fma2(tv2, a2.x, rl2[o4*2]);
            rl2[o4*2+1] = fma2(tv2, a2.y, rl2[o4*2+1]);
            rh2[o4*2]   = fma2(hv2, b2.x, rh2[o4*2]);
            rh2[o4*2+1] = fma2(hv2, b2.y, rh2[o4*2+1]);
        }
    }
    size_t half = (size_t)NB*NC*NPIX;
    #pragma unroll
    for (int j = 0; j < 16; j++) {
        float a, bb; upk2(a, bb, rl2[j]);
        float c2, d2; upk2(c2, d2, rh2[j]);
        int o0 = og + j*2;
        size_t gi0 = ((size_t)(b*NC + o0)*NH + y)*NW + x;
        size_t gi1 = ((size_t)(b*NC + o0 + 1)*NH + y)*NW + x;
        out[gi0]        = low[gi0]  + a;
        out[gi1]        = low[gi1]  + bb;
        out[half + gi0] = high[gi0] + c2;
        out[half + gi1] = high[gi1] + d2;
    }
}

extern "C" void kernel_launch(void* const* d_in, const int* in_sizes, int n_in,
                              void* d_out, int out_size)
{
    (void)in_sizes; (void)n_in; (void)out_size;
    const float* low  = (const float*)d_in[0];
    const float* high = (const float*)d_in[1];
    const float* w_ql = (const float*)d_in[2];
    const float* w_kh = (const float*)d_in[3];
    const float* w_vh = (const float*)d_in[4];
    const float* w_qh = (const float*)d_in[5];
    const float* w_kl = (const float*)d_in[6];
    const float* w_vl = (const float*)d_in[7];
    const float* wpl  = (const float*)d_in[8];
    const float* wph  = (const float*)d_in[9];

    void* pl; cudaGetSymbolAddress(&pl, g_acc_l);
    void* ph; cudaGetSymbolAddress(&ph, g_acc_h);
    cudaMemsetAsync(pl, 0, sizeof(float)*(size_t)NB*NC*NPIX);
    cudaMemsetAsync(ph, 0, sizeof(float)*(size_t)NB*NC*NPIX);

    cudaFuncSetAttribute(proj_kernel, cudaFuncAttributeMaxDynamicSharedMemorySize, (8192+13056)*4);
    cudaFuncSetAttribute(attn_kernel, cudaFuncAttributeMaxDynamicSharedMemorySize, (12288+256)*4);
    cudaFuncSetAttribute(epi_kernel,  cudaFuncAttributeMaxDynamicSharedMemorySize, (16384 + 2*64*WST)*4);

    mean_kernel<<<NB*NC, 256>>>(high);
    se_kernel<<<1, 256>>>((const float*)d_in[10], (const float*)d_in[11],
                          (const float*)d_in[12], (const float*)d_in[13],
                          (const float*)d_in[14], (const float*)d_in[15]);
    proj_kernel<<<dim3(NPIX/64, NB), 256, (8192+13056)*4>>>(low, high, w_ql, w_kh, w_vh, w_qh, w_kl, w_vl);
    attn_kernel<<<dim3(NL, 2, NB), 128, (12288+256)*4>>>();
    epi_kernel<<<dim3(NH, NB), 256, (16384 + 2*64*WST)*4>>>(low, high, wpl, wph, (float*)d_out);
}